// round 6
// baseline (speedup 1.0000x reference)
#include <cuda_runtime.h>
#include <math.h>

#define IN_CH 128
#define HID 64
#define NMAX 50000
#define EMAX 800000

// Scratch (__device__ globals; no allocation allowed)
__device__ int   g_cnt[NMAX];              // in-degree histogram
__device__ int   g_rowptr[NMAX + 1];       // CSR row pointers (by dst)
__device__ int   g_cur[NMAX];              // scatter cursors
__device__ int   g_esrc[EMAX];             // CSR: src node per edge, grouped by dst
__device__ float g_dinv[NMAX];             // 1/sqrt(deg)
__device__ float g_h[NMAX * HID];          // h' = (X@W) * dinv[row] (gather source)
__device__ float g_agg1[NMAX * HID];       // layer-1 aggregation
__device__ float g_agg2[NMAX * HID];       // layer-2 aggregation

// ---------------------------------------------------------------------------
__global__ void zero_cnt_kernel(int n) {
    int i = blockIdx.x * blockDim.x + threadIdx.x;
    if (i < n) g_cnt[i] = 0;
}

__global__ void hist_kernel(const int* __restrict__ dst, int e) {
    int i = blockIdx.x * blockDim.x + threadIdx.x;
    if (i < e) atomicAdd(&g_cnt[__ldg(dst + i)], 1);
}

// single block, 1024 threads: exclusive scan of g_cnt -> rowptr & cur; dinv.
__global__ void scan_kernel(int n) {
    __shared__ int a[1024], b[1024];
    int t = threadIdx.x;
    int chunk = (n + 1023) / 1024;
    int lo = t * chunk, hi = min(lo + chunk, n);
    int s = 0;
    for (int i = lo; i < hi; ++i) s += g_cnt[i];
    a[t] = s;
    __syncthreads();
    int *pin = a, *pout = b;
    for (int off = 1; off < 1024; off <<= 1) {
        pout[t] = pin[t] + (t >= off ? pin[t - off] : 0);
        __syncthreads();
        int* tmp = pin; pin = pout; pout = tmp;
    }
    int run = (t == 0) ? 0 : pin[t - 1];    // exclusive prefix of chunk totals
    for (int i = lo; i < hi; ++i) {
        int c = g_cnt[i];
        g_rowptr[i] = run;
        g_cur[i] = run;
        g_dinv[i] = rsqrtf((float)c + 1.0f);  // +1 self-loop
        run += c;
    }
    if (hi == n && lo <= n) g_rowptr[n] = run;
}

__global__ void scatter_kernel(const int* __restrict__ src, const int* __restrict__ dst, int e) {
    int i = blockIdx.x * blockDim.x + threadIdx.x;
    if (i < e) {
        int d = __ldg(dst + i);
        int p = atomicAdd(&g_cur[d], 1);
        g_esrc[p] = __ldg(src + i);
    }
}

// ---------------------------------------------------------------------------
// GEMM: H[i][c] = dinv[i] * sum_k in[i][k] * W[k][c]
// TRANS: input transform z = relu(dinv[i]*in[i][k] + bIn[k])  (layer-2 input)
// 256 threads -> 64 nodes x 64 cols, 3 CTAs/SM. Thread (tx,ty): cols
// {4tx..+4, 4tx+32..+4}, nodes {2ty, 2ty+1}. Xs row-major pitch K+4
// (X-read banks = (4*node + k) mod 32, 8 consecutive nodes -> conflict-free).
template <int K, bool TRANS>
__global__ void __launch_bounds__(256, 3)
gemm_kernel(const float* __restrict__ X, const float* __restrict__ W,
            const float* __restrict__ bIn, float* __restrict__ H, int n) {
    constexpr int XP = K + 4;
    __shared__ float Ws[K * HID];
    __shared__ float Xs[64 * XP];
    const int t = threadIdx.x;
    const int node0 = blockIdx.x * 64;

    for (int i = t * 4; i < K * HID; i += 1024)
        *(float4*)(Ws + i) = *(const float4*)(W + i);

    // X tile: 4 threads per row, each a quarter of K (float4 loads/stores)
    {
        int r = t >> 2, qd = t & 3;
        int node = node0 + r;
        bool ok = node < n;
        float di = (TRANS && ok) ? g_dinv[node] : 0.f;
#pragma unroll
        for (int g = 0; g < K / 16; ++g) {
            int c = qd * (K / 4) + g * 4;
            float4 v = make_float4(0.f, 0.f, 0.f, 0.f);
            if (ok) {
                v = *(const float4*)(X + node * K + c);
                if (TRANS) {
                    float4 bb = *(const float4*)(bIn + c);
                    v.x = fmaxf(fmaf(di, v.x, bb.x), 0.f);
                    v.y = fmaxf(fmaf(di, v.y, bb.y), 0.f);
                    v.z = fmaxf(fmaf(di, v.z, bb.z), 0.f);
                    v.w = fmaxf(fmaf(di, v.w, bb.w), 0.f);
                }
            }
            *(float4*)(Xs + r * XP + c) = v;
        }
    }
    __syncthreads();

    const int tx = t & 7;
    const int ty = t >> 3;                 // 0..31
    const int cA = tx * 4;
    const int n0 = ty * 2;

    unsigned long long acc[2][4];
#pragma unroll
    for (int m = 0; m < 2; ++m)
#pragma unroll
        for (int p = 0; p < 4; ++p) acc[m][p] = 0ULL;

#pragma unroll 4
    for (int k = 0; k < K; ++k) {
        ulonglong2 wA = *(const ulonglong2*)(Ws + k * HID + cA);
        ulonglong2 wB = *(const ulonglong2*)(Ws + k * HID + cA + 32);
        float x0 = Xs[n0 * XP + k];
        float x1 = Xs[(n0 + 1) * XP + k];
        unsigned long long xx0, xx1;
        asm("mov.b64 %0, {%1, %1};" : "=l"(xx0) : "f"(x0));
        asm("mov.b64 %0, {%1, %1};" : "=l"(xx1) : "f"(x1));
        asm("fma.rn.f32x2 %0, %1, %2, %0;" : "+l"(acc[0][0]) : "l"(wA.x), "l"(xx0));
        asm("fma.rn.f32x2 %0, %1, %2, %0;" : "+l"(acc[0][1]) : "l"(wA.y), "l"(xx0));
        asm("fma.rn.f32x2 %0, %1, %2, %0;" : "+l"(acc[0][2]) : "l"(wB.x), "l"(xx0));
        asm("fma.rn.f32x2 %0, %1, %2, %0;" : "+l"(acc[0][3]) : "l"(wB.y), "l"(xx0));
        asm("fma.rn.f32x2 %0, %1, %2, %0;" : "+l"(acc[1][0]) : "l"(wA.x), "l"(xx1));
        asm("fma.rn.f32x2 %0, %1, %2, %0;" : "+l"(acc[1][1]) : "l"(wA.y), "l"(xx1));
        asm("fma.rn.f32x2 %0, %1, %2, %0;" : "+l"(acc[1][2]) : "l"(wB.x), "l"(xx1));
        asm("fma.rn.f32x2 %0, %1, %2, %0;" : "+l"(acc[1][3]) : "l"(wB.y), "l"(xx1));
    }

#pragma unroll
    for (int m = 0; m < 2; ++m) {
        int node = node0 + n0 + m;
        if (node < n) {
            float di = g_dinv[node];
            float o[8];
            asm("mov.b64 {%0,%1}, %2;" : "=f"(o[0]), "=f"(o[1]) : "l"(acc[m][0]));
            asm("mov.b64 {%0,%1}, %2;" : "=f"(o[2]), "=f"(o[3]) : "l"(acc[m][1]));
            asm("mov.b64 {%0,%1}, %2;" : "=f"(o[4]), "=f"(o[5]) : "l"(acc[m][2]));
            asm("mov.b64 {%0,%1}, %2;" : "=f"(o[6]), "=f"(o[7]) : "l"(acc[m][3]));
            float4 r0 = make_float4(o[0] * di, o[1] * di, o[2] * di, o[3] * di);
            float4 r1 = make_float4(o[4] * di, o[5] * di, o[6] * di, o[7] * di);
            int off = node * HID + cA;
            *(float4*)(H + off) = r0;
            *(float4*)(H + off + 32) = r1;
        }
    }
}

// ---------------------------------------------------------------------------
// CSR aggregation: out[d] = h'[d] + sum_{in-edges} h'[src]. No atomics.
// 16 threads per node (float4 lanes), prefetched index stream.
__global__ void agg_csr_kernel(const float* __restrict__ h, float* __restrict__ out, int n) {
    int tid = blockIdx.x * blockDim.x + threadIdx.x;
    int d = tid >> 4;
    int q = tid & 15;
    if (d >= n) return;
    int beg = __ldg(g_rowptr + d), end = __ldg(g_rowptr + d + 1);
    float4 acc = *(const float4*)(h + d * HID + q * 4);   // self-loop term
    int s = (beg < end) ? __ldg(g_esrc + beg) : 0;
    for (int j = beg; j < end; ++j) {
        int s2 = (j + 1 < end) ? __ldg(g_esrc + j + 1) : 0;
        float4 v = *(const float4*)(h + s * HID + q * 4);
        acc.x += v.x; acc.y += v.y; acc.z += v.z; acc.w += v.w;
        s = s2;
    }
    *(float4*)(out + d * HID + q * 4) = acc;
}

// ---------------------------------------------------------------------------
// decode: out[e] = dot(z[src], z[dst]), z = dinv*agg2 + b2 on the fly.
__global__ void decode_kernel(const int* __restrict__ src, const int* __restrict__ dst,
                              const float* __restrict__ agg, const float* __restrict__ b,
                              float* __restrict__ out, int e) {
    int tid = blockIdx.x * blockDim.x + threadIdx.x;
    int edge = tid >> 4;
    int q = tid & 15;
    if (edge >= e) return;
    int s = __ldg(src + edge);
    int d = __ldg(dst + edge);
    float ds = g_dinv[s], dd = g_dinv[d];
    float4 as = *(const float4*)(agg + s * HID + q * 4);
    float4 ad = *(const float4*)(agg + d * HID + q * 4);
    float4 bb = *(const float4*)(b + q * 4);
    float p;
    {
        float zs = fmaf(ds, as.x, bb.x), zd = fmaf(dd, ad.x, bb.x);
        p = zs * zd;
        zs = fmaf(ds, as.y, bb.y); zd = fmaf(dd, ad.y, bb.y); p = fmaf(zs, zd, p);
        zs = fmaf(ds, as.z, bb.z); zd = fmaf(dd, ad.z, bb.z); p = fmaf(zs, zd, p);
        zs = fmaf(ds, as.w, bb.w); zd = fmaf(dd, ad.w, bb.w); p = fmaf(zs, zd, p);
    }
    p += __shfl_xor_sync(0xffffffffu, p, 8);
    p += __shfl_xor_sync(0xffffffffu, p, 4);
    p += __shfl_xor_sync(0xffffffffu, p, 2);
    p += __shfl_xor_sync(0xffffffffu, p, 1);
    if (q == 0) out[edge] = p;
}

// ---------------------------------------------------------------------------
extern "C" void kernel_launch(void* const* d_in, const int* in_sizes, int n_in,
                              void* d_out, int out_size) {
    const float* x  = (const float*)d_in[0];   // [n, IN_CH]
    const int*   ei = (const int*)d_in[1];     // [2, e]
    const float* W1 = (const float*)d_in[2];
    const float* b1 = (const float*)d_in[3];
    const float* W2 = (const float*)d_in[4];
    const float* b2 = (const float*)d_in[5];
    float* out = (float*)d_out;                // [e]

    int n = in_sizes[0] / IN_CH;
    int e = in_sizes[1] / 2;
    const int* src = ei;
    const int* dst = ei + e;

    float *p_h, *p_agg1, *p_agg2;
    cudaGetSymbolAddress((void**)&p_h, g_h);
    cudaGetSymbolAddress((void**)&p_agg1, g_agg1);
    cudaGetSymbolAddress((void**)&p_agg2, g_agg2);

    const int T = 256;
    int eg = (e * 16 + T - 1) / T;             // 16 lanes per edge
    int ng = (n * 16 + T - 1) / T;             // 16 lanes per node

    // CSR build (by dst) + dinv
    zero_cnt_kernel<<<(n + T - 1) / T, T>>>(n);
    hist_kernel<<<(e + T - 1) / T, T>>>(dst, e);
    scan_kernel<<<1, 1024>>>(n);
    scatter_kernel<<<(e + T - 1) / T, T>>>(src, dst, e);

    // layer 1
    gemm_kernel<IN_CH, false><<<(n + 63) / 64, T>>>(x, W1, nullptr, p_h, n);
    agg_csr_kernel<<<ng, T>>>(p_h, p_agg1, n);

    // layer 2 (z1 = relu(dinv*agg1 + b1) folded into GEMM input load)
    gemm_kernel<HID, true><<<(n + 63) / 64, T>>>(p_agg1, W2, b1, p_h, n);
    agg_csr_kernel<<<ng, T>>>(p_h, p_agg2, n);

    // decode (z2 = dinv*agg2 + b2 folded)
    decode_kernel<<<eg, T>>>(src, dst, p_agg2, b2, out, e);
}

// round 7
// speedup vs baseline: 1.3552x; 1.3552x over previous
#include <cuda_runtime.h>
#include <math.h>

#define IN_CH 128
#define HID 64
#define NMAX 50000
#define EMAX 800000

// Scratch (__device__ globals; no allocation allowed)
__device__ float g_deg[NMAX];              // degree, then dinv in place
__device__ float g_h[NMAX * HID];          // h' = (X@W) * dinv[row]  (gather source)
__device__ float g_agg1[NMAX * HID];       // layer-1 aggregation (init = h' via dual-store)
__device__ float g_agg2[NMAX * HID];       // layer-2 aggregation

// ---------------------------------------------------------------------------
__global__ void init_deg_kernel(int n) {
    int i = blockIdx.x * blockDim.x + threadIdx.x;
    if (i < n) g_deg[i] = 1.0f;            // self-loop contributes 1
}

__global__ void degree_kernel(const int* __restrict__ dst, int e) {
    int i = blockIdx.x * blockDim.x + threadIdx.x;
    if (i < e) {
        float* p = &g_deg[__ldg(dst + i)];
        asm volatile("red.global.add.f32 [%0], %1;" :: "l"(p), "f"(1.0f) : "memory");
    }
}

__global__ void dinv_kernel(int n) {
    int i = blockIdx.x * blockDim.x + threadIdx.x;
    if (i < n) g_deg[i] = rsqrtf(g_deg[i]);
}

// ---------------------------------------------------------------------------
// GEMM: out[i][c] = dinv[i] * sum_k in[i][k] * W[k][c], dual-stored to H and AGG.
// TRANS: input transform z = relu(dinv[i]*in[i][k] + bIn[k])  (layer-2 input)
// 256 threads -> 64 nodes x 64 cols, 3 CTAs/SM (6 warps/SMSP). Thread (tx,ty):
// cols {4tx..+4, 4tx+32..+4}, nodes {2ty, 2ty+1}. Xs row-major pitch K+4.
// Per warp per k: 2 LDS.128 (W, 4-way bcast) + 2 LDS.32 (X, 4-addr bcast) + 8 FFMA2.
template <int K, bool TRANS>
__global__ void __launch_bounds__(256, 3)
gemm_kernel(const float* __restrict__ X, const float* __restrict__ W,
            const float* __restrict__ bIn,
            float* __restrict__ H, float* __restrict__ AGG, int n) {
    constexpr int XP = K + 4;
    __shared__ float Ws[K * HID];
    __shared__ float Xs[64 * XP];
    const int t = threadIdx.x;
    const int node0 = blockIdx.x * 64;

    for (int i = t * 4; i < K * HID; i += 1024)
        *(float4*)(Ws + i) = *(const float4*)(W + i);

    // X tile: 4 threads per row, each a quarter of K (float4 loads/stores)
    {
        int r = t >> 2, qd = t & 3;
        int node = node0 + r;
        bool ok = node < n;
        float di = (TRANS && ok) ? g_deg[node] : 0.f;
#pragma unroll
        for (int g = 0; g < K / 16; ++g) {
            int c = qd * (K / 4) + g * 4;
            float4 v = make_float4(0.f, 0.f, 0.f, 0.f);
            if (ok) {
                v = *(const float4*)(X + node * K + c);
                if (TRANS) {
                    float4 bb = *(const float4*)(bIn + c);
                    v.x = fmaxf(fmaf(di, v.x, bb.x), 0.f);
                    v.y = fmaxf(fmaf(di, v.y, bb.y), 0.f);
                    v.z = fmaxf(fmaf(di, v.z, bb.z), 0.f);
                    v.w = fmaxf(fmaf(di, v.w, bb.w), 0.f);
                }
            }
            *(float4*)(Xs + r * XP + c) = v;
        }
    }
    __syncthreads();

    const int tx = t & 7;
    const int ty = t >> 3;                 // 0..31
    const int cA = tx * 4;
    const int n0 = ty * 2;

    unsigned long long acc[2][4];
#pragma unroll
    for (int m = 0; m < 2; ++m)
#pragma unroll
        for (int p = 0; p < 4; ++p) acc[m][p] = 0ULL;

#pragma unroll 4
    for (int k = 0; k < K; ++k) {
        ulonglong2 wA = *(const ulonglong2*)(Ws + k * HID + cA);
        ulonglong2 wB = *(const ulonglong2*)(Ws + k * HID + cA + 32);
        float x0 = Xs[n0 * XP + k];
        float x1 = Xs[(n0 + 1) * XP + k];
        unsigned long long xx0, xx1;
        asm("mov.b64 %0, {%1, %1};" : "=l"(xx0) : "f"(x0));
        asm("mov.b64 %0, {%1, %1};" : "=l"(xx1) : "f"(x1));
        asm("fma.rn.f32x2 %0, %1, %2, %0;" : "+l"(acc[0][0]) : "l"(wA.x), "l"(xx0));
        asm("fma.rn.f32x2 %0, %1, %2, %0;" : "+l"(acc[0][1]) : "l"(wA.y), "l"(xx0));
        asm("fma.rn.f32x2 %0, %1, %2, %0;" : "+l"(acc[0][2]) : "l"(wB.x), "l"(xx0));
        asm("fma.rn.f32x2 %0, %1, %2, %0;" : "+l"(acc[0][3]) : "l"(wB.y), "l"(xx0));
        asm("fma.rn.f32x2 %0, %1, %2, %0;" : "+l"(acc[1][0]) : "l"(wA.x), "l"(xx1));
        asm("fma.rn.f32x2 %0, %1, %2, %0;" : "+l"(acc[1][1]) : "l"(wA.y), "l"(xx1));
        asm("fma.rn.f32x2 %0, %1, %2, %0;" : "+l"(acc[1][2]) : "l"(wB.x), "l"(xx1));
        asm("fma.rn.f32x2 %0, %1, %2, %0;" : "+l"(acc[1][3]) : "l"(wB.y), "l"(xx1));
    }

#pragma unroll
    for (int m = 0; m < 2; ++m) {
        int node = node0 + n0 + m;
        if (node < n) {
            float di = g_deg[node];
            float o[8];
            asm("mov.b64 {%0,%1}, %2;" : "=f"(o[0]), "=f"(o[1]) : "l"(acc[m][0]));
            asm("mov.b64 {%0,%1}, %2;" : "=f"(o[2]), "=f"(o[3]) : "l"(acc[m][1]));
            asm("mov.b64 {%0,%1}, %2;" : "=f"(o[4]), "=f"(o[5]) : "l"(acc[m][2]));
            asm("mov.b64 {%0,%1}, %2;" : "=f"(o[6]), "=f"(o[7]) : "l"(acc[m][3]));
            float4 r0 = make_float4(o[0] * di, o[1] * di, o[2] * di, o[3] * di);
            float4 r1 = make_float4(o[4] * di, o[5] * di, o[6] * di, o[7] * di);
            int off = node * HID + cA;
            *(float4*)(H + off) = r0;
            *(float4*)(H + off + 32) = r1;
            *(float4*)(AGG + off) = r0;    // self-loop init: agg starts at h'[node]
            *(float4*)(AGG + off + 32) = r1;
        }
    }
}

// ---------------------------------------------------------------------------
// aggregation: agg[dst] += h'[src]  (unweighted; norm folded into producer/consumer)
// 16 lanes per edge, one red.global.add.v4.f32 per lane.
__global__ void agg_kernel(const int* __restrict__ src, const int* __restrict__ dst,
                           const float* __restrict__ h, float* __restrict__ agg, int e) {
    int tid = blockIdx.x * blockDim.x + threadIdx.x;
    int edge = tid >> 4;
    int q = tid & 15;
    if (edge >= e) return;
    int s = __ldg(src + edge);
    int d = __ldg(dst + edge);
    float4 v = *(const float4*)(h + s * HID + q * 4);
    float* p = agg + d * HID + q * 4;
    asm volatile("red.global.add.v4.f32 [%0], {%1,%2,%3,%4};"
                 :: "l"(p), "f"(v.x), "f"(v.y), "f"(v.z), "f"(v.w) : "memory");
}

// ---------------------------------------------------------------------------
// decode: out[e] = dot(z[src], z[dst]), z = dinv*agg2 + b2 on the fly.
// 16 lanes per edge, float4 per lane, shfl-xor reduce within the 16-lane group.
__global__ void decode_kernel(const int* __restrict__ src, const int* __restrict__ dst,
                              const float* __restrict__ agg, const float* __restrict__ b,
                              float* __restrict__ out, int e) {
    int tid = blockIdx.x * blockDim.x + threadIdx.x;
    int edge = tid >> 4;
    int q = tid & 15;
    if (edge >= e) return;
    int s = __ldg(src + edge);
    int d = __ldg(dst + edge);
    float ds = g_deg[s], dd = g_deg[d];
    float4 as = *(const float4*)(agg + s * HID + q * 4);
    float4 ad = *(const float4*)(agg + d * HID + q * 4);
    float4 bb = *(const float4*)(b + q * 4);
    float p;
    {
        float zs = fmaf(ds, as.x, bb.x), zd = fmaf(dd, ad.x, bb.x);
        p = zs * zd;
        zs = fmaf(ds, as.y, bb.y); zd = fmaf(dd, ad.y, bb.y); p = fmaf(zs, zd, p);
        zs = fmaf(ds, as.z, bb.z); zd = fmaf(dd, ad.z, bb.z); p = fmaf(zs, zd, p);
        zs = fmaf(ds, as.w, bb.w); zd = fmaf(dd, ad.w, bb.w); p = fmaf(zs, zd, p);
    }
    p += __shfl_xor_sync(0xffffffffu, p, 8);
    p += __shfl_xor_sync(0xffffffffu, p, 4);
    p += __shfl_xor_sync(0xffffffffu, p, 2);
    p += __shfl_xor_sync(0xffffffffu, p, 1);
    if (q == 0) out[edge] = p;
}

// ---------------------------------------------------------------------------
extern "C" void kernel_launch(void* const* d_in, const int* in_sizes, int n_in,
                              void* d_out, int out_size) {
    const float* x  = (const float*)d_in[0];   // [n, IN_CH]
    const int*   ei = (const int*)d_in[1];     // [2, e]
    const float* W1 = (const float*)d_in[2];
    const float* b1 = (const float*)d_in[3];
    const float* W2 = (const float*)d_in[4];
    const float* b2 = (const float*)d_in[5];
    float* out = (float*)d_out;                // [e]

    int n = in_sizes[0] / IN_CH;
    int e = in_sizes[1] / 2;
    const int* src = ei;
    const int* dst = ei + e;

    float *p_h, *p_agg1, *p_agg2;
    cudaGetSymbolAddress((void**)&p_h, g_h);
    cudaGetSymbolAddress((void**)&p_agg1, g_agg1);
    cudaGetSymbolAddress((void**)&p_agg2, g_agg2);

    const int T = 256;
    int eg = (e * 16 + T - 1) / T;             // 16 lanes per edge

    init_deg_kernel<<<(n + T - 1) / T, T>>>(n);
    degree_kernel<<<(e + T - 1) / T, T>>>(dst, e);
    dinv_kernel<<<(n + T - 1) / T, T>>>(n);

    // layer 1: h' = (X@W1)*dinv, dual-store (agg1 starts at self-loop term)
    gemm_kernel<IN_CH, false><<<(n + 63) / 64, T>>>(x, W1, nullptr, p_h, p_agg1, n);
    agg_kernel<<<eg, T>>>(src, dst, p_h, p_agg1, e);

    // layer 2: input z1 = relu(dinv*agg1 + b1) fused into GEMM load
    gemm_kernel<HID, true><<<(n + 63) / 64, T>>>(p_agg1, W2, b1, p_h, p_agg2, n);
    agg_kernel<<<eg, T>>>(src, dst, p_h, p_agg2, e);

    // decode (z2 = dinv*agg2 + b2 folded)
    decode_kernel<<<eg, T>>>(src, dst, p_agg2, b2, out, e);
}

// round 8
// speedup vs baseline: 1.4462x; 1.0671x over previous
#include <cuda_runtime.h>
#include <math.h>

#define IN_CH 128
#define HID 64
#define NMAX 50000
#define EMAX 800000

// Scratch (__device__ globals; no allocation allowed)
__device__ float g_deg[NMAX];              // degree, then dinv in place
__device__ float g_h[NMAX * HID];          // h' = (X@W) * dinv[row]  (gather source)
__device__ float g_agg1[NMAX * HID];       // layer-1 aggregation (init = h' via dual-store)
__device__ float g_agg2[NMAX * HID];       // layer-2 aggregation

// ---------------------------------------------------------------------------
__global__ void init_deg_kernel(int n) {
    int i = blockIdx.x * blockDim.x + threadIdx.x;
    if (i < n) g_deg[i] = 1.0f;            // self-loop contributes 1
}

__global__ void degree_kernel(const int* __restrict__ dst, int e) {
    int i = blockIdx.x * blockDim.x + threadIdx.x;
    if (i < e) {
        float* p = &g_deg[__ldg(dst + i)];
        asm volatile("red.global.add.f32 [%0], %1;" :: "l"(p), "f"(1.0f) : "memory");
    }
}

__global__ void dinv_kernel(int n) {
    int i = blockIdx.x * blockDim.x + threadIdx.x;
    if (i < n) g_deg[i] = rsqrtf(g_deg[i]);
}

// ---------------------------------------------------------------------------
// GEMM: out[i][c] = dinv[i] * sum_k in[i][k] * W[k][c], dual-stored to H and AGG.
// TRANS: input transform z = relu(dinv[i]*in[i][k] + bIn[k])  (layer-2 input)
// 256 threads -> 64 nodes x 64 cols; K processed in double-buffered chunks of 32
// so smem = 16KB (W) + 18KB (X) = 34KB -> 4 CTAs/SM (32 warps, 8/SMSP).
// Thread (tx,ty): cols {4tx..+4, 4tx+32..+4}, nodes {2ty, 2ty+1}.
template <int K, bool TRANS>
__global__ void __launch_bounds__(256, 4)
gemm_kernel(const float* __restrict__ X, const float* __restrict__ W,
            const float* __restrict__ bIn,
            float* __restrict__ H, float* __restrict__ AGG, int n) {
    constexpr int KC = 32;                 // k-chunk
    constexpr int NC = K / KC;             // #chunks (4 or 2)
    constexpr int XP = KC + 4;             // Xs pitch
    __shared__ float Ws[2][KC * HID];      // [buf][k][col]
    __shared__ float Xs[2][64 * XP];       // [buf][node][k]
    const int t = threadIdx.x;
    const int node0 = blockIdx.x * 64;

    const int xr = t >> 2;                 // X-fill row 0..63
    const int xq = (t & 3) * 8;            // X-fill col offset in chunk
    const int xnode = node0 + xr;
    const bool xok = xnode < n;
    const float xdi = (TRANS && xok) ? g_deg[xnode] : 0.f;

    float4 wreg0, wreg1, xreg0, xreg1;

    // prefetch a chunk into registers
    auto fetch = [&](int c) {
        int kc = c * KC;
        wreg0 = *(const float4*)(W + kc * HID + t * 4);
        wreg1 = *(const float4*)(W + kc * HID + 1024 + t * 4);
        xreg0 = make_float4(0.f, 0.f, 0.f, 0.f);
        xreg1 = make_float4(0.f, 0.f, 0.f, 0.f);
        if (xok) {
            xreg0 = *(const float4*)(X + xnode * K + kc + xq);
            xreg1 = *(const float4*)(X + xnode * K + kc + xq + 4);
            if (TRANS) {
                float4 b0 = *(const float4*)(bIn + kc + xq);
                float4 b1 = *(const float4*)(bIn + kc + xq + 4);
                xreg0.x = fmaxf(fmaf(xdi, xreg0.x, b0.x), 0.f);
                xreg0.y = fmaxf(fmaf(xdi, xreg0.y, b0.y), 0.f);
                xreg0.z = fmaxf(fmaf(xdi, xreg0.z, b0.z), 0.f);
                xreg0.w = fmaxf(fmaf(xdi, xreg0.w, b0.w), 0.f);
                xreg1.x = fmaxf(fmaf(xdi, xreg1.x, b1.x), 0.f);
                xreg1.y = fmaxf(fmaf(xdi, xreg1.y, b1.y), 0.f);
                xreg1.z = fmaxf(fmaf(xdi, xreg1.z, b1.z), 0.f);
                xreg1.w = fmaxf(fmaf(xdi, xreg1.w, b1.w), 0.f);
            }
        }
    };
    auto store = [&](int buf) {
        *(float4*)(&Ws[buf][t * 4]) = wreg0;
        *(float4*)(&Ws[buf][1024 + t * 4]) = wreg1;
        *(float4*)(&Xs[buf][xr * XP + xq]) = xreg0;
        *(float4*)(&Xs[buf][xr * XP + xq + 4]) = xreg1;
    };

    const int tx = t & 7;
    const int ty = t >> 3;                 // 0..31
    const int cA = tx * 4;
    const int n0 = ty * 2;

    unsigned long long acc[2][4];
#pragma unroll
    for (int m = 0; m < 2; ++m)
#pragma unroll
        for (int p = 0; p < 4; ++p) acc[m][p] = 0ULL;

    fetch(0);
    store(0);
    __syncthreads();

#pragma unroll
    for (int c = 0; c < NC; ++c) {
        if (c + 1 < NC) fetch(c + 1);
        const int buf = c & 1;
        const float* ws = Ws[buf];
        const float* xs = Xs[buf];
#pragma unroll
        for (int k = 0; k < KC; ++k) {
            ulonglong2 wA = *(const ulonglong2*)(ws + k * HID + cA);
            ulonglong2 wB = *(const ulonglong2*)(ws + k * HID + cA + 32);
            float x0 = xs[n0 * XP + k];
            float x1 = xs[(n0 + 1) * XP + k];
            unsigned long long xx0, xx1;
            asm("mov.b64 %0, {%1, %1};" : "=l"(xx0) : "f"(x0));
            asm("mov.b64 %0, {%1, %1};" : "=l"(xx1) : "f"(x1));
            asm("fma.rn.f32x2 %0, %1, %2, %0;" : "+l"(acc[0][0]) : "l"(wA.x), "l"(xx0));
            asm("fma.rn.f32x2 %0, %1, %2, %0;" : "+l"(acc[0][1]) : "l"(wA.y), "l"(xx0));
            asm("fma.rn.f32x2 %0, %1, %2, %0;" : "+l"(acc[0][2]) : "l"(wB.x), "l"(xx0));
            asm("fma.rn.f32x2 %0, %1, %2, %0;" : "+l"(acc[0][3]) : "l"(wB.y), "l"(xx0));
            asm("fma.rn.f32x2 %0, %1, %2, %0;" : "+l"(acc[1][0]) : "l"(wA.x), "l"(xx1));
            asm("fma.rn.f32x2 %0, %1, %2, %0;" : "+l"(acc[1][1]) : "l"(wA.y), "l"(xx1));
            asm("fma.rn.f32x2 %0, %1, %2, %0;" : "+l"(acc[1][2]) : "l"(wB.x), "l"(xx1));
            asm("fma.rn.f32x2 %0, %1, %2, %0;" : "+l"(acc[1][3]) : "l"(wB.y), "l"(xx1));
        }
        if (c + 1 < NC) {
            __syncthreads();               // everyone done with buf (c+1)&1
            store((c + 1) & 1);
            __syncthreads();
        }
    }

#pragma unroll
    for (int m = 0; m < 2; ++m) {
        int node = node0 + n0 + m;
        if (node < n) {
            float di = g_deg[node];
            float o[8];
            asm("mov.b64 {%0,%1}, %2;" : "=f"(o[0]), "=f"(o[1]) : "l"(acc[m][0]));
            asm("mov.b64 {%0,%1}, %2;" : "=f"(o[2]), "=f"(o[3]) : "l"(acc[m][1]));
            asm("mov.b64 {%0,%1}, %2;" : "=f"(o[4]), "=f"(o[5]) : "l"(acc[m][2]));
            asm("mov.b64 {%0,%1}, %2;" : "=f"(o[6]), "=f"(o[7]) : "l"(acc[m][3]));
            float4 r0 = make_float4(o[0] * di, o[1] * di, o[2] * di, o[3] * di);
            float4 r1 = make_float4(o[4] * di, o[5] * di, o[6] * di, o[7] * di);
            int off = node * HID + cA;
            *(float4*)(H + off) = r0;
            *(float4*)(H + off + 32) = r1;
            *(float4*)(AGG + off) = r0;    // self-loop init: agg starts at h'[node]
            *(float4*)(AGG + off + 32) = r1;
        }
    }
}

// ---------------------------------------------------------------------------
// aggregation: agg[dst] += h'[src]  (unweighted; norm folded into producer/consumer)
// 16 lanes per edge, one red.global.add.v4.f32 per lane.
__global__ void agg_kernel(const int* __restrict__ src, const int* __restrict__ dst,
                           const float* __restrict__ h, float* __restrict__ agg, int e) {
    int tid = blockIdx.x * blockDim.x + threadIdx.x;
    int edge = tid >> 4;
    int q = tid & 15;
    if (edge >= e) return;
    int s = __ldg(src + edge);
    int d = __ldg(dst + edge);
    float4 v = *(const float4*)(h + s * HID + q * 4);
    float* p = agg + d * HID + q * 4;
    asm volatile("red.global.add.v4.f32 [%0], {%1,%2,%3,%4};"
                 :: "l"(p), "f"(v.x), "f"(v.y), "f"(v.z), "f"(v.w) : "memory");
}

// ---------------------------------------------------------------------------
// decode: out[e] = dot(z[src], z[dst]), z = dinv*agg2 + b2 on the fly.
__global__ void decode_kernel(const int* __restrict__ src, const int* __restrict__ dst,
                              const float* __restrict__ agg, const float* __restrict__ b,
                              float* __restrict__ out, int e) {
    int tid = blockIdx.x * blockDim.x + threadIdx.x;
    int edge = tid >> 4;
    int q = tid & 15;
    if (edge >= e) return;
    int s = __ldg(src + edge);
    int d = __ldg(dst + edge);
    float ds = g_deg[s], dd = g_deg[d];
    float4 as = *(const float4*)(agg + s * HID + q * 4);
    float4 ad = *(const float4*)(agg + d * HID + q * 4);
    float4 bb = *(const float4*)(b + q * 4);
    float p;
    {
        float zs = fmaf(ds, as.x, bb.x), zd = fmaf(dd, ad.x, bb.x);
        p = zs * zd;
        zs = fmaf(ds, as.y, bb.y); zd = fmaf(dd, ad.y, bb.y); p = fmaf(zs, zd, p);
        zs = fmaf(ds, as.z, bb.z); zd = fmaf(dd, ad.z, bb.z); p = fmaf(zs, zd, p);
        zs = fmaf(ds, as.w, bb.w); zd = fmaf(dd, ad.w, bb.w); p = fmaf(zs, zd, p);
    }
    p += __shfl_xor_sync(0xffffffffu, p, 8);
    p += __shfl_xor_sync(0xffffffffu, p, 4);
    p += __shfl_xor_sync(0xffffffffu, p, 2);
    p += __shfl_xor_sync(0xffffffffu, p, 1);
    if (q == 0) out[edge] = p;
}

// ---------------------------------------------------------------------------
extern "C" void kernel_launch(void* const* d_in, const int* in_sizes, int n_in,
                              void* d_out, int out_size) {
    const float* x  = (const float*)d_in[0];   // [n, IN_CH]
    const int*   ei = (const int*)d_in[1];     // [2, e]
    const float* W1 = (const float*)d_in[2];
    const float* b1 = (const float*)d_in[3];
    const float* W2 = (const float*)d_in[4];
    const float* b2 = (const float*)d_in[5];
    float* out = (float*)d_out;                // [e]

    int n = in_sizes[0] / IN_CH;
    int e = in_sizes[1] / 2;
    const int* src = ei;
    const int* dst = ei + e;

    float *p_h, *p_agg1, *p_agg2;
    cudaGetSymbolAddress((void**)&p_h, g_h);
    cudaGetSymbolAddress((void**)&p_agg1, g_agg1);
    cudaGetSymbolAddress((void**)&p_agg2, g_agg2);

    const int T = 256;
    int eg = (e * 16 + T - 1) / T;             // 16 lanes per edge

    init_deg_kernel<<<(n + T - 1) / T, T>>>(n);
    degree_kernel<<<(e + T - 1) / T, T>>>(dst, e);
    dinv_kernel<<<(n + T - 1) / T, T>>>(n);

    // layer 1: h' = (X@W1)*dinv, dual-store (agg1 starts at self-loop term)
    gemm_kernel<IN_CH, false><<<(n + 63) / 64, T>>>(x, W1, nullptr, p_h, p_agg1, n);
    agg_kernel<<<eg, T>>>(src, dst, p_h, p_agg1, e);

    // layer 2: input z1 = relu(dinv*agg1 + b1) fused into GEMM load
    gemm_kernel<HID, true><<<(n + 63) / 64, T>>>(p_agg1, W2, b1, p_h, p_agg2, n);
    agg_kernel<<<eg, T>>>(src, dst, p_h, p_agg2, e);

    // decode (z2 = dinv*agg2 + b2 folded)
    decode_kernel<<<eg, T>>>(src, dst, p_agg2, b2, out, e);
}